// round 5
// baseline (speedup 1.0000x reference)
#include <cuda_runtime.h>
#include <cstdint>

// ---------------- problem constants ----------------
#define Nn     30000
#define F_IN   128
#define F_H    256
#define NHEAD  8
#define CCH    32
#define NEG_SLOPE 0.2f
#define SCAN_T 1024
#define CHUNK  30          // ceil(30000/1024)

// ---------------- device scratch (no allocs allowed) ----------------
__device__ float g_h  [(size_t)Nn * F_H];
__device__ float g_x2 [(size_t)Nn * F_H];
__device__ float g_as [(size_t)Nn * NHEAD];
__device__ float g_ad [(size_t)Nn * NHEAD];
__device__ int   g_count [Nn];
__device__ int   g_rowptr[Nn + 1];
__device__ int   g_cursor[Nn];
__device__ int   g_csrc  [480000 + 1024];   // src list sorted by dst

__device__ __forceinline__ float leaky(float v) {
    return (v > 0.f) ? v : NEG_SLOPE * v;
}
__device__ __forceinline__ unsigned f2tf32(float f) {
    unsigned u;
    asm("cvt.rna.tf32.f32 %0, %1;" : "=r"(u) : "f"(f));
    return u;
}
__device__ __forceinline__ void mma_tf32(float c[4], const unsigned a[4], const unsigned b[2]) {
    asm volatile(
        "mma.sync.aligned.m16n8k8.row.col.f32.tf32.tf32.f32 "
        "{%0,%1,%2,%3}, {%4,%5,%6,%7}, {%8,%9}, {%0,%1,%2,%3};"
        : "+f"(c[0]), "+f"(c[1]), "+f"(c[2]), "+f"(c[3])
        : "r"(a[0]), "r"(a[1]), "r"(a[2]), "r"(a[3]), "r"(b[0]), "r"(b[1]));
}

// ---------------- tf32 MMA GEMM ----------------
#define AP 20
#define BP 136

template <int K>
__global__ void __launch_bounds__(256) k_gemm_tf32(const float* __restrict__ A,
                                                   const float* __restrict__ W,
                                                   float* __restrict__ Cout) {
    __shared__ unsigned As[128 * AP];
    __shared__ unsigned Bs[16 * BP];

    const int tid    = threadIdx.x;
    const int lane   = tid & 31;
    const int warpid = tid >> 5;
    const int row0   = blockIdx.y * 128;
    const int col0   = blockIdx.x * 128;
    const int wm     = (warpid & 3) * 32;
    const int wn     = (warpid >> 2) * 64;
    const int lg     = lane >> 2;
    const int lt     = lane & 3;

    float c[2][8][4];
#pragma unroll
    for (int t = 0; t < 2; t++)
#pragma unroll
        for (int j = 0; j < 8; j++)
#pragma unroll
            for (int r = 0; r < 4; r++) c[t][j][r] = 0.f;

    const int a_row = tid >> 1;
    const int a_c0  = (tid & 1) * 8;
    const int b_k   = tid >> 4;
    const int b_n0  = (tid & 15) * 4;

    for (int k0 = 0; k0 < K; k0 += 16) {
#pragma unroll
        for (int i = 0; i < 2; i++) {
            int col = a_c0 + i * 4;
            float4 v = make_float4(0.f, 0.f, 0.f, 0.f);
            if (row0 + a_row < Nn)
                v = *(const float4*)(A + (size_t)(row0 + a_row) * K + k0 + col);
            *(uint4*)&As[a_row * AP + col] =
                make_uint4(f2tf32(v.x), f2tf32(v.y), f2tf32(v.z), f2tf32(v.w));
        }
#pragma unroll
        for (int i = 0; i < 2; i++) {
            int n = b_n0 + i * 64;
            float4 v = *(const float4*)(W + (size_t)(k0 + b_k) * F_H + col0 + n);
            *(uint4*)&Bs[b_k * BP + n] =
                make_uint4(f2tf32(v.x), f2tf32(v.y), f2tf32(v.z), f2tf32(v.w));
        }
        __syncthreads();

#pragma unroll
        for (int kk = 0; kk < 16; kk += 8) {
            unsigned a[2][4];
#pragma unroll
            for (int t = 0; t < 2; t++) {
                int mr = wm + t * 16;
                a[t][0] = As[(mr + lg) * AP + kk + lt];
                a[t][1] = As[(mr + lg + 8) * AP + kk + lt];
                a[t][2] = As[(mr + lg) * AP + kk + lt + 4];
                a[t][3] = As[(mr + lg + 8) * AP + kk + lt + 4];
            }
#pragma unroll
            for (int j = 0; j < 8; j++) {
                unsigned b[2];
                int n = wn + j * 8 + lg;
                b[0] = Bs[(kk + lt) * BP + n];
                b[1] = Bs[(kk + lt + 4) * BP + n];
                mma_tf32(c[0][j], a[0], b);
                mma_tf32(c[1][j], a[1], b);
            }
        }
        __syncthreads();
    }

#pragma unroll
    for (int t = 0; t < 2; t++) {
        int r0 = row0 + wm + t * 16 + lg;
#pragma unroll
        for (int j = 0; j < 8; j++) {
            int cc = col0 + wn + j * 8 + lt * 2;
            if (r0 < Nn)
                *(float2*)(Cout + (size_t)r0 * F_H + cc) = make_float2(c[t][j][0], c[t][j][1]);
            if (r0 + 8 < Nn)
                *(float2*)(Cout + (size_t)(r0 + 8) * F_H + cc) = make_float2(c[t][j][2], c[t][j][3]);
        }
    }
}

// ---------------- alpha projections ----------------
__global__ void k_alpha(const float* __restrict__ a_src, const float* __restrict__ a_dst) {
    int idx = blockIdx.x * blockDim.x + threadIdx.x;
    if (idx >= Nn * NHEAD) return;
    int n = idx >> 3, h = idx & 7;
    const float4* hp = (const float4*)(g_h + (size_t)n * F_H + h * CCH);
    const float4* as = (const float4*)(a_src + h * CCH);
    const float4* ad = (const float4*)(a_dst + h * CCH);
    float s = 0.f, d = 0.f;
#pragma unroll
    for (int i = 0; i < 8; i++) {
        float4 v = hp[i], a = as[i], b = ad[i];
        s += v.x * a.x + v.y * a.y + v.z * a.z + v.w * a.w;
        d += v.x * b.x + v.y * b.y + v.z * b.z + v.w * b.w;
    }
    g_as[idx] = s;
    g_ad[idx] = d;
}

// ---------------- CSR build ----------------
__global__ void k_zero_count() {
    int i = blockIdx.x * blockDim.x + threadIdx.x;
    if (i < Nn) g_count[i] = 0;
}
__global__ void k_count(const int* __restrict__ ei, int E) {
    int e = blockIdx.x * blockDim.x + threadIdx.x;
    if (e < E) atomicAdd(&g_count[ei[E + e]], 1);
}
__global__ void __launch_bounds__(SCAN_T) k_scan(int E) {
    __shared__ int ssum[SCAN_T];
    int t = threadIdx.x;
    int base = t * CHUNK;
    int s = 0;
#pragma unroll
    for (int i = 0; i < CHUNK; i++) {
        int idx = base + i;
        if (idx < Nn) s += g_count[idx];
    }
    ssum[t] = s;
    __syncthreads();
    for (int off = 1; off < SCAN_T; off <<= 1) {
        int v = (t >= off) ? ssum[t - off] : 0;
        __syncthreads();
        ssum[t] += v;
        __syncthreads();
    }
    int run = ssum[t] - s;   // exclusive prefix for this thread's chunk
#pragma unroll
    for (int i = 0; i < CHUNK; i++) {
        int idx = base + i;
        if (idx < Nn) {
            int c = g_count[idx];
            g_rowptr[idx] = run;
            g_cursor[idx] = run;
            run += c;
        }
    }
    if (t == 0) g_rowptr[Nn] = E;
}
__global__ void k_scatter(const int* __restrict__ ei, int E) {
    int e = blockIdx.x * blockDim.x + threadIdx.x;
    if (e >= E) return;
    int dst = ei[E + e];
    int pos = atomicAdd(&g_cursor[dst], 1);
    g_csrc[pos] = ei[e];
}

// ---------------- fused pull aggregation, layer 1 ----------------
// One block per dst node; warp h owns head h (features h*32+lane).
__global__ void __launch_bounds__(256) k_agg1(const float* __restrict__ b) {
    int n = blockIdx.x;
    int wid = threadIdx.x >> 5, lane = threadIdx.x & 31;
    int f = wid * CCH + lane;
    int beg = g_rowptr[n], end = g_rowptr[n + 1];

    float adn = g_ad[n * NHEAD + wid];
    float ws  = __expf(leaky(g_as[n * NHEAD + wid] + adn));   // self-loop weight
    float den = ws;
    float acc = ws * g_h[(size_t)n * F_H + f];

    int k = beg;
    for (; k + 4 <= end; k += 4) {
        int s0 = g_csrc[k], s1 = g_csrc[k + 1], s2 = g_csrc[k + 2], s3 = g_csrc[k + 3];
        float a0 = __ldg(&g_as[s0 * NHEAD + wid]);
        float a1 = __ldg(&g_as[s1 * NHEAD + wid]);
        float a2 = __ldg(&g_as[s2 * NHEAD + wid]);
        float a3 = __ldg(&g_as[s3 * NHEAD + wid]);
        float h0 = __ldg(&g_h[(size_t)s0 * F_H + f]);
        float h1 = __ldg(&g_h[(size_t)s1 * F_H + f]);
        float h2 = __ldg(&g_h[(size_t)s2 * F_H + f]);
        float h3 = __ldg(&g_h[(size_t)s3 * F_H + f]);
        float w0 = __expf(leaky(a0 + adn)), w1 = __expf(leaky(a1 + adn));
        float w2 = __expf(leaky(a2 + adn)), w3 = __expf(leaky(a3 + adn));
        den += (w0 + w1) + (w2 + w3);
        acc += w0 * h0 + w1 * h1 + w2 * h2 + w3 * h3;
    }
    for (; k < end; k++) {
        int s = g_csrc[k];
        float w = __expf(leaky(__ldg(&g_as[s * NHEAD + wid]) + adn));
        den += w;
        acc += w * __ldg(&g_h[(size_t)s * F_H + f]);
    }

    float v = acc / den + b[f];
    g_x2[(size_t)n * F_H + f] = (v > 0.f) ? v : expm1f(v);
}

// ---------------- fused pull aggregation, layer 2 + linear head ----------------
__global__ void __launch_bounds__(256) k_agg2(const float* __restrict__ b2,
                                              const float* __restrict__ Wl,
                                              const float* __restrict__ bl,
                                              float* __restrict__ out) {
    __shared__ float part[NHEAD];
    int n = blockIdx.x;
    int wid = threadIdx.x >> 5, lane = threadIdx.x & 31;
    int f = wid * CCH + lane;
    int beg = g_rowptr[n], end = g_rowptr[n + 1];

    float adn = g_ad[n * NHEAD + wid];
    float ws  = __expf(leaky(g_as[n * NHEAD + wid] + adn));
    float den = ws;
    float acc = ws * g_h[(size_t)n * F_H + f];

    int k = beg;
    for (; k + 4 <= end; k += 4) {
        int s0 = g_csrc[k], s1 = g_csrc[k + 1], s2 = g_csrc[k + 2], s3 = g_csrc[k + 3];
        float a0 = __ldg(&g_as[s0 * NHEAD + wid]);
        float a1 = __ldg(&g_as[s1 * NHEAD + wid]);
        float a2 = __ldg(&g_as[s2 * NHEAD + wid]);
        float a3 = __ldg(&g_as[s3 * NHEAD + wid]);
        float h0 = __ldg(&g_h[(size_t)s0 * F_H + f]);
        float h1 = __ldg(&g_h[(size_t)s1 * F_H + f]);
        float h2 = __ldg(&g_h[(size_t)s2 * F_H + f]);
        float h3 = __ldg(&g_h[(size_t)s3 * F_H + f]);
        float w0 = __expf(leaky(a0 + adn)), w1 = __expf(leaky(a1 + adn));
        float w2 = __expf(leaky(a2 + adn)), w3 = __expf(leaky(a3 + adn));
        den += (w0 + w1) + (w2 + w3);
        acc += w0 * h0 + w1 * h1 + w2 * h2 + w3 * h3;
    }
    for (; k < end; k++) {
        int s = g_csrc[k];
        float w = __expf(leaky(__ldg(&g_as[s * NHEAD + wid]) + adn));
        den += w;
        acc += w * __ldg(&g_h[(size_t)s * F_H + f]);
    }

    float v = acc / den + b2[f];
    v = (v > 0.f) ? v : expm1f(v);
    float p = v * Wl[f];
#pragma unroll
    for (int o = 16; o > 0; o >>= 1) p += __shfl_down_sync(0xFFFFFFFFu, p, o);
    if (lane == 0) part[wid] = p;
    __syncthreads();
    if (threadIdx.x == 0) {
        float s = bl[0];
#pragma unroll
        for (int i = 0; i < NHEAD; i++) s += part[i];
        out[n] = s;
    }
}

// ---------------- host ----------------
extern "C" void kernel_launch(void* const* d_in, const int* in_sizes, int n_in,
                              void* d_out, int out_size) {
    const float* x   = (const float*)d_in[0];
    const int*   ei  = (const int*)  d_in[1];
    const float* W1  = (const float*)d_in[2];
    const float* a1s = (const float*)d_in[3];
    const float* a1d = (const float*)d_in[4];
    const float* b1  = (const float*)d_in[5];
    const float* W2  = (const float*)d_in[6];
    const float* a2s = (const float*)d_in[7];
    const float* a2d = (const float*)d_in[8];
    const float* b2  = (const float*)d_in[9];
    const float* Wl  = (const float*)d_in[10];
    const float* bl  = (const float*)d_in[11];
    float* out = (float*)d_out;

    const int E = in_sizes[1] / 2;          // 480000

    float* g_h_p;  cudaGetSymbolAddress((void**)&g_h_p,  g_h);
    float* g_x2_p; cudaGetSymbolAddress((void**)&g_x2_p, g_x2);

    const int T = 256;
    dim3 gemm_grid(F_H / 128, (Nn + 127) / 128);
    int nh_blocks = (Nn * NHEAD + T - 1) / T;
    int e_blocks  = (E + T - 1) / T;

    // ---------- CSR build (shared by both layers) ----------
    k_zero_count<<<(Nn + T - 1) / T, T>>>();
    k_count<<<e_blocks, T>>>(ei, E);
    k_scan<<<1, SCAN_T>>>(E);
    k_scatter<<<e_blocks, T>>>(ei, E);

    // ---------- layer 1 ----------
    k_gemm_tf32<F_IN><<<gemm_grid, T>>>(x, W1, g_h_p);
    k_alpha<<<nh_blocks, T>>>(a1s, a1d);
    k_agg1<<<Nn, T>>>(b1);

    // ---------- layer 2 ----------
    k_gemm_tf32<F_H><<<gemm_grid, T>>>(g_x2_p, W2, g_h_p);
    k_alpha<<<nh_blocks, T>>>(a2s, a2d);
    k_agg2<<<Nn, T>>>(b2, Wl, bl, out);
}

// round 6
// speedup vs baseline: 1.1817x; 1.1817x over previous
#include <cuda_runtime.h>
#include <cstdint>

// ---------------- problem constants ----------------
#define Nn     30000
#define F_IN   128
#define F_H    256
#define NHEAD  8
#define CCH    32
#define NEG_SLOPE 0.2f
#define SCAN_T 1024
#define CHUNK  30          // ceil(30000/1024)
#define ETILE  128         // edges staged per smem tile

// ---------------- device scratch (no allocs allowed) ----------------
__device__ float g_h  [(size_t)Nn * F_H];
__device__ float g_x2 [(size_t)Nn * F_H];
__device__ float g_as [(size_t)Nn * NHEAD];
__device__ float g_ad [(size_t)Nn * NHEAD];
__device__ int   g_count [Nn];
__device__ int   g_rowptr[Nn + 1];
__device__ int   g_cursor[Nn];
__device__ int   g_csrc  [480000 + 1024];   // src list grouped by dst

__device__ __forceinline__ float leaky(float v) {
    return (v > 0.f) ? v : NEG_SLOPE * v;
}
__device__ __forceinline__ unsigned f2tf32(float f) {
    unsigned u;
    asm("cvt.rna.tf32.f32 %0, %1;" : "=r"(u) : "f"(f));
    return u;
}
__device__ __forceinline__ void mma_tf32(float c[4], const unsigned a[4], const unsigned b[2]) {
    asm volatile(
        "mma.sync.aligned.m16n8k8.row.col.f32.tf32.tf32.f32 "
        "{%0,%1,%2,%3}, {%4,%5,%6,%7}, {%8,%9}, {%0,%1,%2,%3};"
        : "+f"(c[0]), "+f"(c[1]), "+f"(c[2]), "+f"(c[3])
        : "r"(a[0]), "r"(a[1]), "r"(a[2]), "r"(a[3]), "r"(b[0]), "r"(b[1]));
}

// ---------------- tf32 MMA GEMM ----------------
#define AP 20
#define BP 136

template <int K>
__global__ void __launch_bounds__(256) k_gemm_tf32(const float* __restrict__ A,
                                                   const float* __restrict__ W,
                                                   float* __restrict__ Cout) {
    __shared__ unsigned As[128 * AP];
    __shared__ unsigned Bs[16 * BP];

    const int tid    = threadIdx.x;
    const int lane   = tid & 31;
    const int warpid = tid >> 5;
    const int row0   = blockIdx.y * 128;
    const int col0   = blockIdx.x * 128;
    const int wm     = (warpid & 3) * 32;
    const int wn     = (warpid >> 2) * 64;
    const int lg     = lane >> 2;
    const int lt     = lane & 3;

    float c[2][8][4];
#pragma unroll
    for (int t = 0; t < 2; t++)
#pragma unroll
        for (int j = 0; j < 8; j++)
#pragma unroll
            for (int r = 0; r < 4; r++) c[t][j][r] = 0.f;

    const int a_row = tid >> 1;
    const int a_c0  = (tid & 1) * 8;
    const int b_k   = tid >> 4;
    const int b_n0  = (tid & 15) * 4;

    for (int k0 = 0; k0 < K; k0 += 16) {
#pragma unroll
        for (int i = 0; i < 2; i++) {
            int col = a_c0 + i * 4;
            float4 v = make_float4(0.f, 0.f, 0.f, 0.f);
            if (row0 + a_row < Nn)
                v = *(const float4*)(A + (size_t)(row0 + a_row) * K + k0 + col);
            *(uint4*)&As[a_row * AP + col] =
                make_uint4(f2tf32(v.x), f2tf32(v.y), f2tf32(v.z), f2tf32(v.w));
        }
#pragma unroll
        for (int i = 0; i < 2; i++) {
            int n = b_n0 + i * 64;
            float4 v = *(const float4*)(W + (size_t)(k0 + b_k) * F_H + col0 + n);
            *(uint4*)&Bs[b_k * BP + n] =
                make_uint4(f2tf32(v.x), f2tf32(v.y), f2tf32(v.z), f2tf32(v.w));
        }
        __syncthreads();

#pragma unroll
        for (int kk = 0; kk < 16; kk += 8) {
            unsigned a[2][4];
#pragma unroll
            for (int t = 0; t < 2; t++) {
                int mr = wm + t * 16;
                a[t][0] = As[(mr + lg) * AP + kk + lt];
                a[t][1] = As[(mr + lg + 8) * AP + kk + lt];
                a[t][2] = As[(mr + lg) * AP + kk + lt + 4];
                a[t][3] = As[(mr + lg + 8) * AP + kk + lt + 4];
            }
#pragma unroll
            for (int j = 0; j < 8; j++) {
                unsigned b[2];
                int n = wn + j * 8 + lg;
                b[0] = Bs[(kk + lt) * BP + n];
                b[1] = Bs[(kk + lt + 4) * BP + n];
                mma_tf32(c[0][j], a[0], b);
                mma_tf32(c[1][j], a[1], b);
            }
        }
        __syncthreads();
    }

#pragma unroll
    for (int t = 0; t < 2; t++) {
        int r0 = row0 + wm + t * 16 + lg;
#pragma unroll
        for (int j = 0; j < 8; j++) {
            int cc = col0 + wn + j * 8 + lt * 2;
            if (r0 < Nn)
                *(float2*)(Cout + (size_t)r0 * F_H + cc) = make_float2(c[t][j][0], c[t][j][1]);
            if (r0 + 8 < Nn)
                *(float2*)(Cout + (size_t)(r0 + 8) * F_H + cc) = make_float2(c[t][j][2], c[t][j][3]);
        }
    }
}

// ---------------- alpha projections ----------------
__global__ void k_alpha(const float* __restrict__ a_src, const float* __restrict__ a_dst) {
    int idx = blockIdx.x * blockDim.x + threadIdx.x;
    if (idx >= Nn * NHEAD) return;
    int n = idx >> 3, h = idx & 7;
    const float4* hp = (const float4*)(g_h + (size_t)n * F_H + h * CCH);
    const float4* as = (const float4*)(a_src + h * CCH);
    const float4* ad = (const float4*)(a_dst + h * CCH);
    float s = 0.f, d = 0.f;
#pragma unroll
    for (int i = 0; i < 8; i++) {
        float4 v = hp[i], a = as[i], b = ad[i];
        s += v.x * a.x + v.y * a.y + v.z * a.z + v.w * a.w;
        d += v.x * b.x + v.y * b.y + v.z * b.z + v.w * b.w;
    }
    g_as[idx] = s;
    g_ad[idx] = d;
}

// ---------------- CSR build ----------------
__global__ void k_zero_count() {
    int i = blockIdx.x * blockDim.x + threadIdx.x;
    if (i < Nn) g_count[i] = 0;
}
__global__ void k_count(const int* __restrict__ ei, int E) {
    int e = blockIdx.x * blockDim.x + threadIdx.x;
    if (e < E) atomicAdd(&g_count[ei[E + e]], 1);
}
__global__ void __launch_bounds__(SCAN_T) k_scan(int E) {
    __shared__ int ssum[SCAN_T];
    int t = threadIdx.x;
    int base = t * CHUNK;
    int s = 0;
#pragma unroll
    for (int i = 0; i < CHUNK; i++) {
        int idx = base + i;
        if (idx < Nn) s += g_count[idx];
    }
    ssum[t] = s;
    __syncthreads();
    for (int off = 1; off < SCAN_T; off <<= 1) {
        int v = (t >= off) ? ssum[t - off] : 0;
        __syncthreads();
        ssum[t] += v;
        __syncthreads();
    }
    int run = ssum[t] - s;
#pragma unroll
    for (int i = 0; i < CHUNK; i++) {
        int idx = base + i;
        if (idx < Nn) {
            int c = g_count[idx];
            g_rowptr[idx] = run;
            g_cursor[idx] = run;
            run += c;
        }
    }
    if (t == 0) g_rowptr[Nn] = E;
}
__global__ void k_scatter(const int* __restrict__ ei, int E) {
    int e = blockIdx.x * blockDim.x + threadIdx.x;
    if (e >= E) return;
    int dst = ei[E + e];
    int pos = atomicAdd(&g_cursor[dst], 1);
    g_csrc[pos] = ei[e];
}

// ---------------- fused pull aggregation with smem staging ----------------
// One block per dst node, 256 threads. Warp h owns head h (feature f = h*32+lane).
// Phase A: stage src indices + all edge-head weights in smem (breaks the
//          csrc->h dependency chain). Phase B: stream h rows with unroll-8.
template <bool FINAL>
__global__ void __launch_bounds__(256) k_agg(const float* __restrict__ b,
                                             const float* __restrict__ Wl,
                                             const float* __restrict__ bl,
                                             float* __restrict__ out) {
    __shared__ int   ssrc[ETILE];
    __shared__ float sw  [ETILE * NHEAD];
    __shared__ float sad [NHEAD];
    __shared__ float part[NHEAD];

    const int n   = blockIdx.x;
    const int tid = threadIdx.x;
    const int wid = tid >> 5, lane = tid & 31;
    const int f   = wid * CCH + lane;
    const int beg = g_rowptr[n], end = g_rowptr[n + 1];

    if (tid < NHEAD) sad[tid] = g_ad[n * NHEAD + tid];
    __syncthreads();

    const float adn = sad[wid];
    const float ws  = __expf(leaky(g_as[n * NHEAD + wid] + adn));   // self loop
    float den = ws;
    float acc = ws * g_h[(size_t)n * F_H + f];

    for (int tb = beg; tb < end; tb += ETILE) {
        const int cnt = min(ETILE, end - tb);
        // --- stage src indices (coalesced) ---
        for (int i = tid; i < cnt; i += 256) ssrc[i] = g_csrc[tb + i];
        __syncthreads();
        // --- compute all edge-head weights (coalesced 32B granules of g_as) ---
        for (int t = tid; t < cnt * NHEAD; t += 256) {
            int s = ssrc[t >> 3];
            sw[t] = __expf(leaky(__ldg(&g_as[s * NHEAD + (t & 7)]) + sad[t & 7]));
        }
        __syncthreads();
        // --- gather phase: unroll-8 independent 128B row loads ---
        int k = 0;
        for (; k + 8 <= cnt; k += 8) {
            int   s[8];
            float w[8], hv[8];
#pragma unroll
            for (int i = 0; i < 8; i++) s[i] = ssrc[k + i];
#pragma unroll
            for (int i = 0; i < 8; i++) w[i] = sw[(k + i) * NHEAD + wid];
#pragma unroll
            for (int i = 0; i < 8; i++) hv[i] = __ldg(&g_h[(size_t)s[i] * F_H + f]);
#pragma unroll
            for (int i = 0; i < 8; i++) { den += w[i]; acc += w[i] * hv[i]; }
        }
        for (; k < cnt; k++) {
            int s = ssrc[k];
            float w = sw[k * NHEAD + wid];
            den += w;
            acc += w * __ldg(&g_h[(size_t)s * F_H + f]);
        }
        __syncthreads();   // before smem reuse next tile
    }

    float v = acc / den + b[f];
    v = (v > 0.f) ? v : expm1f(v);

    if (!FINAL) {
        g_x2[(size_t)n * F_H + f] = v;
    } else {
        float p = v * Wl[f];
#pragma unroll
        for (int o = 16; o > 0; o >>= 1) p += __shfl_down_sync(0xFFFFFFFFu, p, o);
        if (lane == 0) part[wid] = p;
        __syncthreads();
        if (tid == 0) {
            float s = bl[0];
#pragma unroll
            for (int i = 0; i < NHEAD; i++) s += part[i];
            out[n] = s;
        }
    }
}

// ---------------- host ----------------
extern "C" void kernel_launch(void* const* d_in, const int* in_sizes, int n_in,
                              void* d_out, int out_size) {
    const float* x   = (const float*)d_in[0];
    const int*   ei  = (const int*)  d_in[1];
    const float* W1  = (const float*)d_in[2];
    const float* a1s = (const float*)d_in[3];
    const float* a1d = (const float*)d_in[4];
    const float* b1  = (const float*)d_in[5];
    const float* W2  = (const float*)d_in[6];
    const float* a2s = (const float*)d_in[7];
    const float* a2d = (const float*)d_in[8];
    const float* b2  = (const float*)d_in[9];
    const float* Wl  = (const float*)d_in[10];
    const float* bl  = (const float*)d_in[11];
    float* out = (float*)d_out;

    const int E = in_sizes[1] / 2;          // 480000

    float* g_h_p;  cudaGetSymbolAddress((void**)&g_h_p,  g_h);
    float* g_x2_p; cudaGetSymbolAddress((void**)&g_x2_p, g_x2);

    const int T = 256;
    dim3 gemm_grid(F_H / 128, (Nn + 127) / 128);
    int nh_blocks = (Nn * NHEAD + T - 1) / T;
    int e_blocks  = (E + T - 1) / T;

    // ---------- CSR build (shared by both layers) ----------
    k_zero_count<<<(Nn + T - 1) / T, T>>>();
    k_count<<<e_blocks, T>>>(ei, E);
    k_scan<<<1, SCAN_T>>>(E);
    k_scatter<<<e_blocks, T>>>(ei, E);

    // ---------- layer 1 ----------
    k_gemm_tf32<F_IN><<<gemm_grid, T>>>(x, W1, g_h_p);
    k_alpha<<<nh_blocks, T>>>(a1s, a1d);
    k_agg<false><<<Nn, T>>>(b1, nullptr, nullptr, nullptr);

    // ---------- layer 2 ----------
    k_gemm_tf32<F_H><<<gemm_grid, T>>>(g_x2_p, W2, g_h_p);
    k_alpha<<<nh_blocks, T>>>(a2s, a2d);
    k_agg<true><<<Nn, T>>>(b2, Wl, bl, out);
}